// round 16
// baseline (speedup 1.0000x reference)
#include <cuda_runtime.h>
#include <cuda_bf16.h>
#include <cuda_fp16.h>
#include <cstdint>

#define BB 4
#define SS 4096
#define DD 512
#define HH 64

typedef unsigned long long u64;

// fp16 operands for attention (single-rounded). Q pre-scaled by log2(e)/8.
// V transposed [b][h][s].
__device__ __align__(16) __half g_qh[BB*SS*HH];
__device__ __align__(16) __half g_kh[BB*SS*HH];
__device__ __align__(16) __half g_vth[BB*SS*HH];
// Pre-converted transposed weights (single fp16): [mat][h][d].
__device__ __align__(16) __half g_wth[3*HH*DD];

// ======================= small helpers ======================================
__device__ __forceinline__ float ex2f(float x) {
    float r; asm("ex2.approx.f32 %0, %1;" : "=f"(r) : "f"(x)); return r;
}
// pack two floats into f16x2: low half = lo, high half = hi.
__device__ __forceinline__ uint32_t hfpack(float lo, float hi) {
    uint32_t r;
    asm("cvt.rn.f16x2.f32 %0, %1, %2;" : "=r"(r) : "f"(hi), "f"(lo));
    return r;
}
__device__ __forceinline__ float2 h2f2(uint32_t h) {
    __half2 v = *reinterpret_cast<__half2*>(&h);
    return __half22float2(v);
}

// ======================= tensor-core primitives =============================
__device__ __forceinline__ uint32_t smem_u32(const void* p) {
    uint32_t a;
    asm("{ .reg .u64 t; cvta.to.shared.u64 t, %1; cvt.u32.u64 %0, t; }"
        : "=r"(a) : "l"(p));
    return a;
}
__device__ __forceinline__ void mma_f16(float (&d)[4], const uint32_t (&a)[4],
                                        uint32_t b0, uint32_t b1) {
    asm volatile(
        "mma.sync.aligned.m16n8k16.row.col.f32.f16.f16.f32 "
        "{%0,%1,%2,%3}, {%4,%5,%6,%7}, {%8,%9}, {%0,%1,%2,%3};"
        : "+f"(d[0]), "+f"(d[1]), "+f"(d[2]), "+f"(d[3])
        : "r"(a[0]), "r"(a[1]), "r"(a[2]), "r"(a[3]), "r"(b0), "r"(b1));
}
__device__ __forceinline__ void ldsm_x4(uint32_t (&r)[4], uint32_t addr) {
    asm volatile("ldmatrix.sync.aligned.m8n8.x4.shared.b16 {%0,%1,%2,%3}, [%4];"
        : "=r"(r[0]), "=r"(r[1]), "=r"(r[2]), "=r"(r[3]) : "r"(addr));
}
__device__ __forceinline__ void cp16(uint32_t saddr, const void* gaddr) {
    asm volatile("cp.async.cg.shared.global [%0], [%1], 16;"
        :: "r"(saddr), "l"(gaddr));
}
#define CP_COMMIT() asm volatile("cp.async.commit_group;" ::: "memory")
#define CP_WAIT(n)  asm volatile("cp.async.wait_group %0;" :: "n"(n) : "memory")

// ---------------------------------------------------------------------------
// Kernel 0: pre-convert W (transposed) to fp16. [mat][h][d]
// ---------------------------------------------------------------------------
__global__ void wsplit_kernel(const float* __restrict__ Wq,
                              const float* __restrict__ Wk,
                              const float* __restrict__ Wv) {
    int i = blockIdx.x * 256 + threadIdx.x;
#pragma unroll
    for (int e = 0; e < 4; ++e, i += 24576) {
        int mat = i >> 15;
        int rem = i & 32767;
        int h = rem >> 9;
        int d = rem & 511;
        const float* W = mat == 0 ? Wq : (mat == 1 ? Wk : Wv);
        g_wth[i] = __float2half_rn(W[d * 64 + h]);
    }
}

// ---------------------------------------------------------------------------
// Kernel 1: QKV projection via HMMA fp16 single-term (verified R14).
// ---------------------------------------------------------------------------
#define QKV_XF(s) ((s) * 32768)
#define QKV_W(s)  (65536 + (s) * 24576)
#define QKV_XH    114688
#define QKV_SMEM  131072

__device__ __forceinline__ void qkv_load_x(uint32_t sb, const float* __restrict__ x,
                                           int row0, int kb, int slot, int tid) {
    const int row = tid >> 1;
    const int c0 = (tid & 1) * 8;
    const float* src = x + (size_t)(row0 + row) * 512 + kb * 64 + c0 * 4;
    const uint32_t dst = sb + QKV_XF(slot) + row * 256 + c0 * 16;
#pragma unroll
    for (int c = 0; c < 8; ++c) cp16(dst + c * 16, src + c * 4);
}

__device__ __forceinline__ void qkv_load_w(uint32_t sb, int kb, int slot, int tid) {
    if (tid < 192) {
        const int mat = tid >> 6;
        const int h = tid & 63;
        const __half* src = g_wth + ((size_t)(mat * 64 + h)) * 512 + kb * 64;
        const uint32_t dst = sb + QKV_W(slot) + mat * 8192 + h * 128;
        const int sw = h & 7;
#pragma unroll
        for (int c = 0; c < 8; ++c) cp16(dst + ((c ^ sw) << 4), src + c * 8);
    }
}

__global__ void __launch_bounds__(256, 1) qkv_kernel(
    const float* __restrict__ x,
    const float* __restrict__ bq, const float* __restrict__ bk,
    const float* __restrict__ bv)
{
    extern __shared__ __align__(1024) unsigned char sm[];
    const uint32_t sb = smem_u32(sm);

    const int tid  = threadIdx.x;
    const int lane = tid & 31;
    const int wid  = tid >> 5;
    const int row0 = blockIdx.x * 128;

    qkv_load_x(sb, x, row0, 0, 0, tid);
    qkv_load_w(sb, 0, 0, tid);
    CP_COMMIT();
    qkv_load_x(sb, x, row0, 1, 1, tid);
    qkv_load_w(sb, 1, 1, tid);
    CP_COMMIT();

    float acc[3][8][4] = {};

    const int g = lane >> 3, l = lane & 7;
    const int rowA = wid * 16 + l + ((g & 1) << 3);
    const int cA = g >> 1;
    const int swA = rowA & 7;
    const int rowB = l + ((g & 2) << 2);
    const int cB = g & 1;
    const int swB = rowB & 7;

    for (int kb = 0; kb < 8; ++kb) {
        CP_WAIT(1);
        __syncthreads();

        // Convert fp32 x chunk -> single fp16, swizzled.
        {
            const int row = tid >> 1;
            const int p0 = (tid & 1) * 16;
            const float* srow = (const float*)(sm + QKV_XF(kb & 1)) + row * 64;
#pragma unroll
            for (int pp = 0; pp < 16; ++pp) {
                const int cp = p0 + pp;
                uint32_t h = hfpack(srow[cp * 2], srow[cp * 2 + 1]);
                const uint32_t a = (uint32_t)(row * 128 +
                                   (((cp >> 2) ^ (row & 7)) << 4) + (cp & 3) * 4);
                *(uint32_t*)(sm + QKV_XH + a) = h;
            }
        }
        __syncthreads();

        const uint32_t wbase = sb + QKV_W(kb & 1);
#pragma unroll
        for (int kc = 0; kc < 4; ++kc) {
            uint32_t aXH[4];
            const uint32_t offA = (uint32_t)(rowA * 128 +
                                 ((((kc << 1) | cA) ^ swA) << 4));
            ldsm_x4(aXH, sb + QKV_XH + offA);
#pragma unroll
            for (int mat = 0; mat < 3; ++mat) {
#pragma unroll
                for (int jj = 0; jj < 4; ++jj) {
                    const uint32_t offB = (uint32_t)((jj * 16 + rowB) * 128 +
                                         ((((kc << 1) | cB) ^ swB) << 4));
                    uint32_t bh[4];
                    ldsm_x4(bh, wbase + mat * 8192 + offB);
                    mma_f16(acc[mat][2*jj],   aXH, bh[0], bh[1]);
                    mma_f16(acc[mat][2*jj+1], aXH, bh[2], bh[3]);
                }
            }
        }
        __syncthreads();

        if (kb + 2 < 8) {
            qkv_load_x(sb, x, row0, kb + 2, kb & 1, tid);
            qkv_load_w(sb, kb + 2, kb & 1, tid);
        }
        CP_COMMIT();
    }

    // Epilogue: bias, Q-scale, single fp16 stores (+ V transposed).
    const float QSC = 0.18033688011112042f;   // log2(e)/8
    const int r = lane >> 2;
    const int cq = (lane & 3);
    const int tok = row0 + wid * 16 + r;
    const int bb = blockIdx.x >> 5;
    const int s  = (row0 & (SS - 1)) + wid * 16 + r;

    uint32_t* qhA = (uint32_t*)(g_qh + (size_t)tok * 64);
    uint32_t* qhB = (uint32_t*)(g_qh + (size_t)(tok + 8) * 64);
    uint32_t* khA = (uint32_t*)(g_kh + (size_t)tok * 64);
    uint32_t* khB = (uint32_t*)(g_kh + (size_t)(tok + 8) * 64);

#pragma unroll
    for (int j = 0; j < 8; ++j) {
        const int u32idx = j * 4 + cq;
        const float2 b2q = ((const float2*)bq)[u32idx];
        const float2 b2k = ((const float2*)bk)[u32idx];
        const float2 b2v = ((const float2*)bv)[u32idx];

        qhA[u32idx] = hfpack((acc[0][j][0] + b2q.x) * QSC,
                             (acc[0][j][1] + b2q.y) * QSC);
        qhB[u32idx] = hfpack((acc[0][j][2] + b2q.x) * QSC,
                             (acc[0][j][3] + b2q.y) * QSC);

        khA[u32idx] = hfpack(acc[1][j][0] + b2k.x, acc[1][j][1] + b2k.y);
        khB[u32idx] = hfpack(acc[1][j][2] + b2k.x, acc[1][j][3] + b2k.y);

        {
            const int c0 = j * 8 + cq * 2;
            size_t r0 = ((size_t)(bb * 64 + c0)) * SS;
            size_t r1 = r0 + SS;
            g_vth[r0 + s]     = __float2half_rn(acc[2][j][0] + b2v.x);
            g_vth[r1 + s]     = __float2half_rn(acc[2][j][1] + b2v.y);
            g_vth[r0 + s + 8] = __float2half_rn(acc[2][j][2] + b2v.x);
            g_vth[r1 + s + 8] = __float2half_rn(acc[2][j][3] + b2v.y);
        }
    }
}

// ---------------------------------------------------------------------------
// Kernel 2: attn13 — R15 attn12 with a 6-slot ring and ONE barrier per TWO
// key tiles. Compute bodies unchanged. Grid (64,4) x 128 thr. Smem 104 KB.
// ---------------------------------------------------------------------------
#define STAGE_BYTES 16384
#define QOFF 98304
#define ATTN_SMEM (QOFF + 8192)

__device__ __forceinline__ void load_stage128(uint32_t sb, int b, int kt, int slot, int tid) {
    const int row = tid >> 1;
    const int sel = tid & 1;   // 0: K row, 1: V row
    const __half* src = sel
        ? g_vth + (size_t)(b * HH + row) * SS + kt * 64
        : g_kh  + (size_t)(b * SS + kt * 64 + row) * 64;
    const uint32_t dst = sb + slot * STAGE_BYTES + sel * 8192 + row * 128;
    const int sw = row & 7;
#pragma unroll
    for (int c = 0; c < 8; ++c) cp16(dst + ((c ^ sw) << 4), src + c * 8);
}

__global__ void __launch_bounds__(128, 2) attn13_kernel(float* __restrict__ out)
{
    extern __shared__ __align__(1024) unsigned char sm[];

    const int tid  = threadIdx.x;
    const int lane = tid & 31;
    const int wid  = tid >> 5;
    const int qt = blockIdx.x;
    const int b  = blockIdx.y;
    const int tok0 = b * SS + qt * 64;
    const uint32_t sb = smem_u32(sm);

    // Prologue groups: Q (g0), tiles {0,1} (g1), tiles {2,3} (g2).
    {
        const int row = tid >> 1;
        const int c0 = (tid & 1) * 4;
        const int sw = row & 7;
        const __half* qh = g_qh + (size_t)(tok0 + row) * 64;
#pragma unroll
        for (int c = 0; c < 4; ++c) {
            const int ch = c0 + c;
            cp16(sb + QOFF + (uint32_t)(row * 128 + ((ch ^ sw) << 4)), qh + ch * 8);
        }
    }
    CP_COMMIT();
    load_stage128(sb, b, 0, 0, tid);
    load_stage128(sb, b, 1, 1, tid);
    CP_COMMIT();
    load_stage128(sb, b, 2, 2, tid);
    load_stage128(sb, b, 3, 3, tid);
    CP_COMMIT();

    // Q fragments (Q group done; tile groups may be in flight).
    CP_WAIT(2);
    __syncthreads();
    uint32_t aQH[4][4];
    {
        const int g = lane >> 3, l = lane & 7;
        const int rowA = wid * 16 + l + ((g & 1) << 3);
        const int cA = g >> 1;
        const int swA = rowA & 7;
#pragma unroll
        for (int kc = 0; kc < 4; ++kc) {
            const uint32_t offA =
                (uint32_t)(rowA * 128 + ((((kc << 1) | cA) ^ swA) << 4));
            ldsm_x4(aQH[kc], sb + QOFF + offA);
        }
    }

    float O[8][4] = {};
    float lsum0 = 0.f, lsum1 = 0.f;

    const int g = lane >> 3, l = lane & 7;
    const int rowB = l + ((g & 2) << 2);
    const int cB = g & 1;
    const int swB = rowB & 7;

    // 6-slot ring; tile t lives in slot t % 6.
    for (int it = 0; it < 64; it += 2) {
        CP_WAIT(1);          // tiles it, it+1 complete (next pair may be in flight)
        __syncthreads();     // all warps past iteration it-2 reads; data visible

        // Issue loads for tiles it+4, it+5 into slots last read at iter it-2.
        if (it + 4 < 64) {
            load_stage128(sb, b, it + 4, (it + 4) % 6, tid);
            load_stage128(sb, b, it + 5, (it + 5) % 6, tid);
        }
        CP_COMMIT();

#pragma unroll
        for (int sub = 0; sub < 2; ++sub) {
            const uint32_t st = sb + (uint32_t)((it + sub) % 6) * STAGE_BYTES;

            // ---- GEMM1: S = Qh * Kh ----
            float S[8][4] = {};
#pragma unroll
            for (int kc = 0; kc < 4; ++kc) {
#pragma unroll
                for (int j2 = 0; j2 < 4; ++j2) {
                    const uint32_t offB = (uint32_t)((j2 * 16 + rowB) * 128 +
                                         ((((kc << 1) | cB) ^ swB) << 4));
                    uint32_t bh[4];
                    ldsm_x4(bh, st + offB);
                    mma_f16(S[2*j2],   aQH[kc], bh[0], bh[1]);
                    mma_f16(S[2*j2+1], aQH[kc], bh[2], bh[3]);
                }
            }

            // ---- p = 2^s via MUFU; round to fp16; lsum from rounded ----
            uint32_t aPH[4][4];
#pragma unroll
            for (int j = 0; j < 8; ++j) {
                float p0 = ex2f(S[j][0]);
                float p1 = ex2f(S[j][1]);
                float p2 = ex2f(S[j][2]);
                float p3 = ex2f(S[j][3]);
                uint32_t h01 = hfpack(p0, p1);
                uint32_t h23 = hfpack(p2, p3);
                float2 r01 = h2f2(h01);
                float2 r23 = h2f2(h23);
                lsum0 += r01.x + r01.y;
                lsum1 += r23.x + r23.y;
                aPH[j >> 1][(j & 1) * 2 + 0] = h01;
                aPH[j >> 1][(j & 1) * 2 + 1] = h23;
            }

            // ---- GEMM2: O += Ph * Vh ----
#pragma unroll
            for (int kc = 0; kc < 4; ++kc) {
#pragma unroll
                for (int j2 = 0; j2 < 4; ++j2) {
                    const uint32_t offB = (uint32_t)((j2 * 16 + rowB) * 128 +
                                         ((((kc << 1) | cB) ^ swB) << 4));
                    uint32_t bh[4];
                    ldsm_x4(bh, st + 8192 + offB);
                    mma_f16(O[2*j2],   aPH[kc], bh[0], bh[1]);
                    mma_f16(O[2*j2+1], aPH[kc], bh[2], bh[3]);
                }
            }
        }
        // no trailing barrier — next iteration's single sync covers WAR
    }

    lsum0 += __shfl_xor_sync(0xffffffffu, lsum0, 1);
    lsum0 += __shfl_xor_sync(0xffffffffu, lsum0, 2);
    lsum1 += __shfl_xor_sync(0xffffffffu, lsum1, 1);
    lsum1 += __shfl_xor_sync(0xffffffffu, lsum1, 2);
    const float inv0 = 1.0f / lsum0;
    const float inv1 = 1.0f / lsum1;

    const int r  = lane >> 2;
    const int cc = (lane & 3) * 2;
    const size_t qrow = (size_t)tok0 + wid * 16 + r;
#pragma unroll
    for (int j = 0; j < 8; ++j) {
        float2* p0 = (float2*)(out + qrow * 64 + j * 8 + cc);
        *p0 = make_float2(O[j][0] * inv0, O[j][1] * inv0);
        float2* p1 = (float2*)(out + (qrow + 8) * 64 + j * 8 + cc);
        *p1 = make_float2(O[j][2] * inv1, O[j][3] * inv1);
    }
}

extern "C" void kernel_launch(void* const* d_in, const int* in_sizes, int n_in,
                              void* d_out, int out_size) {
    (void)in_sizes; (void)n_in; (void)out_size;
    const float* x  = (const float*)d_in[0];
    const float* Wq = (const float*)d_in[1];
    const float* bq = (const float*)d_in[2];
    const float* Wk = (const float*)d_in[3];
    const float* bk = (const float*)d_in[4];
    const float* Wv = (const float*)d_in[5];
    const float* bv = (const float*)d_in[6];

    cudaFuncSetAttribute(qkv_kernel,
                         cudaFuncAttributeMaxDynamicSharedMemorySize, QKV_SMEM);
    cudaFuncSetAttribute(attn13_kernel,
                         cudaFuncAttributeMaxDynamicSharedMemorySize, ATTN_SMEM);

    wsplit_kernel<<<96, 256>>>(Wq, Wk, Wv);
    qkv_kernel<<<128, 256, QKV_SMEM>>>(x, bq, bk, bv);
    attn13_kernel<<<dim3(64, 4), 128, ATTN_SMEM>>>((float*)d_out);
}

// round 17
// speedup vs baseline: 1.0423x; 1.0423x over previous
#include <cuda_runtime.h>
#include <cuda_bf16.h>
#include <cuda_fp16.h>
#include <cstdint>

#define BB 4
#define SS 4096
#define DD 512
#define HH 64

typedef unsigned long long u64;

// fp16 operands for attention (single-rounded). Q pre-scaled by log2(e)/8.
// V transposed [b][h][s].
__device__ __align__(16) __half g_qh[BB*SS*HH];
__device__ __align__(16) __half g_kh[BB*SS*HH];
__device__ __align__(16) __half g_vth[BB*SS*HH];
// Pre-converted transposed weights (single fp16): [mat][h][d].
__device__ __align__(16) __half g_wth[3*HH*DD];

// ======================= small helpers ======================================
__device__ __forceinline__ float ex2f(float x) {
    float r; asm("ex2.approx.f32 %0, %1;" : "=f"(r) : "f"(x)); return r;
}
// pack two floats into f16x2: low half = lo, high half = hi.
__device__ __forceinline__ uint32_t hfpack(float lo, float hi) {
    uint32_t r;
    asm("cvt.rn.f16x2.f32 %0, %1, %2;" : "=r"(r) : "f"(hi), "f"(lo));
    return r;
}
__device__ __forceinline__ float2 h2f2(uint32_t h) {
    __half2 v = *reinterpret_cast<__half2*>(&h);
    return __half22float2(v);
}

// ======================= tensor-core primitives =============================
__device__ __forceinline__ uint32_t smem_u32(const void* p) {
    uint32_t a;
    asm("{ .reg .u64 t; cvta.to.shared.u64 t, %1; cvt.u32.u64 %0, t; }"
        : "=r"(a) : "l"(p));
    return a;
}
__device__ __forceinline__ void mma_f16(float (&d)[4], const uint32_t (&a)[4],
                                        uint32_t b0, uint32_t b1) {
    asm volatile(
        "mma.sync.aligned.m16n8k16.row.col.f32.f16.f16.f32 "
        "{%0,%1,%2,%3}, {%4,%5,%6,%7}, {%8,%9}, {%0,%1,%2,%3};"
        : "+f"(d[0]), "+f"(d[1]), "+f"(d[2]), "+f"(d[3])
        : "r"(a[0]), "r"(a[1]), "r"(a[2]), "r"(a[3]), "r"(b0), "r"(b1));
}
__device__ __forceinline__ void ldsm_x4(uint32_t (&r)[4], uint32_t addr) {
    asm volatile("ldmatrix.sync.aligned.m8n8.x4.shared.b16 {%0,%1,%2,%3}, [%4];"
        : "=r"(r[0]), "=r"(r[1]), "=r"(r[2]), "=r"(r[3]) : "r"(addr));
}
__device__ __forceinline__ void cp16(uint32_t saddr, const void* gaddr) {
    asm volatile("cp.async.cg.shared.global [%0], [%1], 16;"
        :: "r"(saddr), "l"(gaddr));
}
#define CP_COMMIT() asm volatile("cp.async.commit_group;" ::: "memory")
#define CP_WAIT(n)  asm volatile("cp.async.wait_group %0;" :: "n"(n) : "memory")

// ---------------------------------------------------------------------------
// Kernel 0: pre-convert W (transposed) to fp16. [mat][h][d]
// ---------------------------------------------------------------------------
__global__ void wsplit_kernel(const float* __restrict__ Wq,
                              const float* __restrict__ Wk,
                              const float* __restrict__ Wv) {
    int i = blockIdx.x * 256 + threadIdx.x;
#pragma unroll
    for (int e = 0; e < 4; ++e, i += 24576) {
        int mat = i >> 15;
        int rem = i & 32767;
        int h = rem >> 9;
        int d = rem & 511;
        const float* W = mat == 0 ? Wq : (mat == 1 ? Wk : Wv);
        g_wth[i] = __float2half_rn(W[d * 64 + h]);
    }
}

// ---------------------------------------------------------------------------
// Kernel 1: QKV projection via HMMA fp16 single-term, now 256 CTAs x 128 thr
// (64 token rows each), 2 CTAs/SM to hide per-phase latency.
// Smem: xf32 2x16K @0; W 2x24K @32768; XH 8K @81920. Total 90112.
// ---------------------------------------------------------------------------
#define QKV_XF(s) ((s) * 16384)
#define QKV_W(s)  (32768 + (s) * 24576)
#define QKV_XH    81920
#define QKV_SMEM  90112

__device__ __forceinline__ void qkv_load_x(uint32_t sb, const float* __restrict__ x,
                                           int row0, int kb, int slot, int tid) {
    const int row = tid >> 1;               // 0..63
    const int c0 = (tid & 1) * 8;
    const float* src = x + (size_t)(row0 + row) * 512 + kb * 64 + c0 * 4;
    const uint32_t dst = sb + QKV_XF(slot) + row * 256 + c0 * 16;
#pragma unroll
    for (int c = 0; c < 8; ++c) cp16(dst + c * 16, src + c * 4);
}

__device__ __forceinline__ void qkv_load_w(uint32_t sb, int kb, int slot, int tid) {
#pragma unroll
    for (int u = tid; u < 192; u += 128) {
        const int mat = u >> 6;
        const int h = u & 63;
        const __half* src = g_wth + ((size_t)(mat * 64 + h)) * 512 + kb * 64;
        const uint32_t dst = sb + QKV_W(slot) + mat * 8192 + h * 128;
        const int sw = h & 7;
#pragma unroll
        for (int c = 0; c < 8; ++c) cp16(dst + ((c ^ sw) << 4), src + c * 8);
    }
}

__global__ void __launch_bounds__(128, 2) qkv_kernel(
    const float* __restrict__ x,
    const float* __restrict__ bq, const float* __restrict__ bk,
    const float* __restrict__ bv)
{
    extern __shared__ __align__(1024) unsigned char sm[];
    const uint32_t sb = smem_u32(sm);

    const int tid  = threadIdx.x;
    const int lane = tid & 31;
    const int wid  = tid >> 5;             // 0..3
    const int row0 = blockIdx.x * 64;

    qkv_load_x(sb, x, row0, 0, 0, tid);
    qkv_load_w(sb, 0, 0, tid);
    CP_COMMIT();
    qkv_load_x(sb, x, row0, 1, 1, tid);
    qkv_load_w(sb, 1, 1, tid);
    CP_COMMIT();

    float acc[3][8][4] = {};

    const int g = lane >> 3, l = lane & 7;
    const int rowA = wid * 16 + l + ((g & 1) << 3);
    const int cA = g >> 1;
    const int swA = rowA & 7;
    const int rowB = l + ((g & 2) << 2);
    const int cB = g & 1;
    const int swB = rowB & 7;

    for (int kb = 0; kb < 8; ++kb) {
        CP_WAIT(1);
        __syncthreads();

        // Convert fp32 x chunk -> single fp16, swizzled. 64 rows x 32 pairs.
        {
            const int row = tid >> 1;            // 0..63
            const int p0 = (tid & 1) * 16;
            const float* srow = (const float*)(sm + QKV_XF(kb & 1)) + row * 64;
#pragma unroll
            for (int pp = 0; pp < 16; ++pp) {
                const int cp = p0 + pp;
                uint32_t h = hfpack(srow[cp * 2], srow[cp * 2 + 1]);
                const uint32_t a = (uint32_t)(row * 128 +
                                   (((cp >> 2) ^ (row & 7)) << 4) + (cp & 3) * 4);
                *(uint32_t*)(sm + QKV_XH + a) = h;
            }
        }
        __syncthreads();

        const uint32_t wbase = sb + QKV_W(kb & 1);
#pragma unroll
        for (int kc = 0; kc < 4; ++kc) {
            uint32_t aXH[4];
            const uint32_t offA = (uint32_t)(rowA * 128 +
                                 ((((kc << 1) | cA) ^ swA) << 4));
            ldsm_x4(aXH, sb + QKV_XH + offA);
#pragma unroll
            for (int mat = 0; mat < 3; ++mat) {
#pragma unroll
                for (int jj = 0; jj < 4; ++jj) {
                    const uint32_t offB = (uint32_t)((jj * 16 + rowB) * 128 +
                                         ((((kc << 1) | cB) ^ swB) << 4));
                    uint32_t bh[4];
                    ldsm_x4(bh, wbase + mat * 8192 + offB);
                    mma_f16(acc[mat][2*jj],   aXH, bh[0], bh[1]);
                    mma_f16(acc[mat][2*jj+1], aXH, bh[2], bh[3]);
                }
            }
        }
        __syncthreads();

        if (kb + 2 < 8) {
            qkv_load_x(sb, x, row0, kb + 2, kb & 1, tid);
            qkv_load_w(sb, kb + 2, kb & 1, tid);
        }
        CP_COMMIT();
    }

    // Epilogue: bias, Q-scale, single fp16 stores (+ V transposed).
    const float QSC = 0.18033688011112042f;   // log2(e)/8
    const int r = lane >> 2;
    const int cq = (lane & 3);
    const int tok = row0 + wid * 16 + r;
    const int bb = blockIdx.x >> 6;            // 64 CTAs per batch
    const int s  = (row0 & (SS - 1)) + wid * 16 + r;

    uint32_t* qhA = (uint32_t*)(g_qh + (size_t)tok * 64);
    uint32_t* qhB = (uint32_t*)(g_qh + (size_t)(tok + 8) * 64);
    uint32_t* khA = (uint32_t*)(g_kh + (size_t)tok * 64);
    uint32_t* khB = (uint32_t*)(g_kh + (size_t)(tok + 8) * 64);

#pragma unroll
    for (int j = 0; j < 8; ++j) {
        const int u32idx = j * 4 + cq;
        const float2 b2q = ((const float2*)bq)[u32idx];
        const float2 b2k = ((const float2*)bk)[u32idx];
        const float2 b2v = ((const float2*)bv)[u32idx];

        qhA[u32idx] = hfpack((acc[0][j][0] + b2q.x) * QSC,
                             (acc[0][j][1] + b2q.y) * QSC);
        qhB[u32idx] = hfpack((acc[0][j][2] + b2q.x) * QSC,
                             (acc[0][j][3] + b2q.y) * QSC);

        khA[u32idx] = hfpack(acc[1][j][0] + b2k.x, acc[1][j][1] + b2k.y);
        khB[u32idx] = hfpack(acc[1][j][2] + b2k.x, acc[1][j][3] + b2k.y);

        {
            const int c0 = j * 8 + cq * 2;
            size_t r0 = ((size_t)(bb * 64 + c0)) * SS;
            size_t r1 = r0 + SS;
            g_vth[r0 + s]     = __float2half_rn(acc[2][j][0] + b2v.x);
            g_vth[r1 + s]     = __float2half_rn(acc[2][j][1] + b2v.y);
            g_vth[r0 + s + 8] = __float2half_rn(acc[2][j][2] + b2v.x);
            g_vth[r1 + s + 8] = __float2half_rn(acc[2][j][3] + b2v.y);
        }
    }
}

// ---------------------------------------------------------------------------
// Kernel 2: attn12 — R15 verified (~93us). MUFU ex2 softmax, 3-slot ring,
// one barrier per tile. Grid (64,4) x 128 thr. Dyn smem 56 KB.
// ---------------------------------------------------------------------------
#define STAGE_BYTES 16384
#define QOFF 49152
#define ATTN_SMEM (QOFF + 8192)

__device__ __forceinline__ void load_stage128(uint32_t sb, int b, int kt, int stage, int tid) {
    const int row = tid >> 1;
    const int sel = tid & 1;   // 0: K row, 1: V row
    const __half* src = sel
        ? g_vth + (size_t)(b * HH + row) * SS + kt * 64
        : g_kh  + (size_t)(b * SS + kt * 64 + row) * 64;
    const uint32_t dst = sb + stage * STAGE_BYTES + sel * 8192 + row * 128;
    const int sw = row & 7;
#pragma unroll
    for (int c = 0; c < 8; ++c) cp16(dst + ((c ^ sw) << 4), src + c * 8);
}

__global__ void __launch_bounds__(128, 2) attn12_kernel(float* __restrict__ out)
{
    extern __shared__ __align__(1024) unsigned char sm[];

    const int tid  = threadIdx.x;
    const int lane = tid & 31;
    const int wid  = tid >> 5;
    const int qt = blockIdx.x;
    const int b  = blockIdx.y;
    const int tok0 = b * SS + qt * 64;
    const uint32_t sb = smem_u32(sm);

    // Prologue groups: Q, tile0, tile1.
    {
        const int row = tid >> 1;
        const int c0 = (tid & 1) * 4;
        const int sw = row & 7;
        const __half* qh = g_qh + (size_t)(tok0 + row) * 64;
#pragma unroll
        for (int c = 0; c < 4; ++c) {
            const int ch = c0 + c;
            cp16(sb + QOFF + (uint32_t)(row * 128 + ((ch ^ sw) << 4)), qh + ch * 8);
        }
    }
    CP_COMMIT();
    load_stage128(sb, b, 0, 0, tid);
    CP_COMMIT();
    load_stage128(sb, b, 1, 1, tid);
    CP_COMMIT();

    // Q fragments (Q group done; tiles 0,1 still possibly in flight).
    CP_WAIT(2);
    __syncthreads();
    uint32_t aQH[4][4];
    {
        const int g = lane >> 3, l = lane & 7;
        const int rowA = wid * 16 + l + ((g & 1) << 3);
        const int cA = g >> 1;
        const int swA = rowA & 7;
#pragma unroll
        for (int kc = 0; kc < 4; ++kc) {
            const uint32_t offA =
                (uint32_t)(rowA * 128 + ((((kc << 1) | cA) ^ swA) << 4));
            ldsm_x4(aQH[kc], sb + QOFF + offA);
        }
    }

    float O[8][4] = {};
    float lsum0 = 0.f, lsum1 = 0.f;

    const int g = lane >> 3, l = lane & 7;
    const int rowB = l + ((g & 2) << 2);
    const int cB = g & 1;
    const int swB = rowB & 7;

    int stage = 0;       // stage of tile kt
    int lstage = 2;      // ring slot for tile kt+2
    for (int kt = 0; kt < 64; ++kt) {
        CP_WAIT(1);          // tile kt's group complete
        __syncthreads();     // visibility + all warps past phase kt-1 reads

        if (kt + 2 < 64) load_stage128(sb, b, kt + 2, lstage, tid);
        CP_COMMIT();
        if (++lstage == 3) lstage = 0;

        const uint32_t st = sb + (uint32_t)stage * STAGE_BYTES;
        if (++stage == 3) stage = 0;

        // ---- GEMM1: S = Qh * Kh ----
        float S[8][4] = {};
#pragma unroll
        for (int kc = 0; kc < 4; ++kc) {
#pragma unroll
            for (int j2 = 0; j2 < 4; ++j2) {
                const uint32_t offB = (uint32_t)((j2 * 16 + rowB) * 128 +
                                     ((((kc << 1) | cB) ^ swB) << 4));
                uint32_t bh[4];
                ldsm_x4(bh, st + offB);
                mma_f16(S[2*j2],   aQH[kc], bh[0], bh[1]);
                mma_f16(S[2*j2+1], aQH[kc], bh[2], bh[3]);
            }
        }

        // ---- p = 2^s via MUFU ex2.approx; round to fp16; lsum from rounded ----
        uint32_t aPH[4][4];
#pragma unroll
        for (int j = 0; j < 8; ++j) {
            float p0 = ex2f(S[j][0]);
            float p1 = ex2f(S[j][1]);
            float p2 = ex2f(S[j][2]);
            float p3 = ex2f(S[j][3]);
            uint32_t h01 = hfpack(p0, p1);
            uint32_t h23 = hfpack(p2, p3);
            float2 r01 = h2f2(h01);
            float2 r23 = h2f2(h23);
            lsum0 += r01.x + r01.y;
            lsum1 += r23.x + r23.y;
            aPH[j >> 1][(j & 1) * 2 + 0] = h01;
            aPH[j >> 1][(j & 1) * 2 + 1] = h23;
        }

        // ---- GEMM2: O += Ph * Vh ----
#pragma unroll
        for (int kc = 0; kc < 4; ++kc) {
#pragma unroll
            for (int j2 = 0; j2 < 4; ++j2) {
                const uint32_t offB = (uint32_t)((j2 * 16 + rowB) * 128 +
                                     ((((kc << 1) | cB) ^ swB) << 4));
                uint32_t bh[4];
                ldsm_x4(bh, st + 8192 + offB);
                mma_f16(O[2*j2],   aPH[kc], bh[0], bh[1]);
                mma_f16(O[2*j2+1], aPH[kc], bh[2], bh[3]);
            }
        }
        // no trailing barrier — next phase's single sync covers the WAR hazard
    }

    lsum0 += __shfl_xor_sync(0xffffffffu, lsum0, 1);
    lsum0 += __shfl_xor_sync(0xffffffffu, lsum0, 2);
    lsum1 += __shfl_xor_sync(0xffffffffu, lsum1, 1);
    lsum1 += __shfl_xor_sync(0xffffffffu, lsum1, 2);
    const float inv0 = 1.0f / lsum0;
    const float inv1 = 1.0f / lsum1;

    const int r  = lane >> 2;
    const int cc = (lane & 3) * 2;
    const size_t qrow = (size_t)tok0 + wid * 16 + r;
#pragma unroll
    for (int j = 0; j < 8; ++j) {
        float2* p0 = (float2*)(out + qrow * 64 + j * 8 + cc);
        *p0 = make_float2(O[j][0] * inv0, O[j][1] * inv0);
        float2* p1 = (float2*)(out + (qrow + 8) * 64 + j * 8 + cc);
        *p1 = make_float2(O[j][2] * inv1, O[j][3] * inv1);
    }
}

extern "C" void kernel_launch(void* const* d_in, const int* in_sizes, int n_in,
                              void* d_out, int out_size) {
    (void)in_sizes; (void)n_in; (void)out_size;
    const float* x  = (const float*)d_in[0];
    const float* Wq = (const float*)d_in[1];
    const float* bq = (const float*)d_in[2];
    const float* Wk = (const float*)d_in[3];
    const float* bk = (const float*)d_in[4];
    const float* Wv = (const float*)d_in[5];
    const float* bv = (const float*)d_in[6];

    cudaFuncSetAttribute(qkv_kernel,
                         cudaFuncAttributeMaxDynamicSharedMemorySize, QKV_SMEM);
    cudaFuncSetAttribute(attn12_kernel,
                         cudaFuncAttributeMaxDynamicSharedMemorySize, ATTN_SMEM);

    wsplit_kernel<<<96, 256>>>(Wq, Wk, Wv);
    qkv_kernel<<<256, 128, QKV_SMEM>>>(x, bq, bk, bv);
    attn12_kernel<<<dim3(64, 4), 128, ATTN_SMEM>>>((float*)d_out);
}